// round 6
// baseline (speedup 1.0000x reference)
#include <cuda_runtime.h>
#include <cuda_bf16.h>
#include <cstdint>

#define SSn 2048
#define DDn 64
#define HHn 16
#define BBn 4
#define L2E 1.4426950408889634f

#define ROWB 144                 // smem row stride (conflict-free ldmatrix)
#define LOFFA (64 * ROWB)        // hi->lo offset within one buffer (9216)
#define BUFSZ (2 * 64 * ROWB)    // one buffer: hi+lo (18432)

__device__ float g_inv[BBn * HHn * SSn];

__device__ __forceinline__ uint32_t smem_u32(const void* p) {
    uint32_t a;
    asm("{ .reg .u64 t; cvta.to.shared.u64 t, %1; cvt.u32.u64 %0, t; }" : "=r"(a) : "l"(p));
    return a;
}
__device__ __forceinline__ void mma16816(float* c, const uint32_t* a, const uint32_t* b) {
    asm volatile("mma.sync.aligned.m16n8k16.row.col.f32.bf16.bf16.f32 "
        "{%0,%1,%2,%3}, {%4,%5,%6,%7}, {%8,%9}, {%0,%1,%2,%3};"
        : "+f"(c[0]), "+f"(c[1]), "+f"(c[2]), "+f"(c[3])
        : "r"(a[0]), "r"(a[1]), "r"(a[2]), "r"(a[3]), "r"(b[0]), "r"(b[1]));
}
__device__ __forceinline__ void ldsm4(uint32_t* r, uint32_t a) {
    asm volatile("ldmatrix.sync.aligned.m8n8.x4.shared.b16 {%0,%1,%2,%3}, [%4];"
        : "=r"(r[0]), "=r"(r[1]), "=r"(r[2]), "=r"(r[3]) : "r"(a));
}
__device__ __forceinline__ void ldsm4t(uint32_t* r, uint32_t a) {
    asm volatile("ldmatrix.sync.aligned.m8n8.x4.trans.shared.b16 {%0,%1,%2,%3}, [%4];"
        : "=r"(r[0]), "=r"(r[1]), "=r"(r[2]), "=r"(r[3]) : "r"(a));
}
__device__ __forceinline__ void split2(float x, float y, uint32_t& hp, uint32_t& lp) {
    __nv_bfloat162 h2 = __float22bfloat162_rn(make_float2(x, y));
    float2 hf = __bfloat1622float2(h2);
    __nv_bfloat162 l2 = __float22bfloat162_rn(make_float2(x - hf.x, y - hf.y));
    hp = *reinterpret_cast<uint32_t*>(&h2);
    lp = *reinterpret_cast<uint32_t*>(&l2);
}
__device__ __forceinline__ float ex2(float x) {
    float y; asm("ex2.approx.f32 %0, %1;" : "=f"(y) : "f"(x)); return y;
}

// =====================================================================
// Kernel A: exp((Q/8)K^T + bias + mask) -> Attn (UNNORMALIZED); 1/rowsum -> g_inv
// 64-key chunks, double-buffered smem, register-prefetched gmem loads.
// =====================================================================
__global__ __launch_bounds__(256) void attn_scores_kernel(
    const float* __restrict__ Q, const float* __restrict__ K,
    const float* __restrict__ Bias, const float* __restrict__ Mask,
    float* __restrict__ Attn)
{
    __shared__ __align__(16) char sK[2 * BUFSZ];

    const int tid = threadIdx.x, wid = tid >> 5, lane = tid & 31;
    const int b = blockIdx.x, h = blockIdx.y, qt = blockIdx.z;
    const int bh = b * HHn + h, q0 = qt * 128;
    const int rA = wid * 16 + (lane >> 2);
    const int kA = (lane & 3) * 2;

    // Q A-fragments, scaled 1/8, split hi/lo (register-resident)
    uint32_t a_hi[4][4], a_lo[4][4];
    {
        const float* q_r0 = Q + ((size_t)bh * SSn + q0 + rA) * DDn;
        const float* q_r1 = q_r0 + 8 * DDn;
        #pragma unroll
        for (int ks = 0; ks < 4; ++ks) {
            float2 v;
            v = *(const float2*)(q_r0 + ks * 16 + kA);
            split2(v.x * 0.125f, v.y * 0.125f, a_hi[ks][0], a_lo[ks][0]);
            v = *(const float2*)(q_r1 + ks * 16 + kA);
            split2(v.x * 0.125f, v.y * 0.125f, a_hi[ks][1], a_lo[ks][1]);
            v = *(const float2*)(q_r0 + ks * 16 + 8 + kA);
            split2(v.x * 0.125f, v.y * 0.125f, a_hi[ks][2], a_lo[ks][2]);
            v = *(const float2*)(q_r1 + ks * 16 + 8 + kA);
            split2(v.x * 0.125f, v.y * 0.125f, a_hi[ks][3], a_lo[ks][3]);
        }
    }

    const uint32_t sb = smem_u32(sK);
    const float4* Ks = (const float4*)(K + (size_t)bh * SSn * DDn);

    float4 kv[4];
    #pragma unroll
    for (int i = 0; i < 4; ++i) kv[i] = Ks[tid + i * 256];        // chunk 0

    {   // store chunk 0 into buffer 0
        #pragma unroll
        for (int i = 0; i < 4; ++i) {
            int f4 = tid + i * 256, row = f4 >> 4, c4 = f4 & 15;
            uint32_t h0, l0, h1, l1;
            split2(kv[i].x, kv[i].y, h0, l0);
            split2(kv[i].z, kv[i].w, h1, l1);
            char* d = sK + row * ROWB + c4 * 8;
            *(uint2*)d = make_uint2(h0, h1);
            *(uint2*)(d + LOFFA) = make_uint2(l0, l1);
        }
    }
    __syncthreads();

    const float* brow0 = Bias + ((size_t)h * SSn + q0 + rA) * SSn;
    const float* brow1 = brow0 + 8 * SSn;
    const float* mrow0 = Mask + ((size_t)b * SSn + q0 + rA) * SSn;
    const float* mrow1 = mrow0 + 8 * SSn;
    float* arow0 = Attn + ((size_t)bh * SSn + q0 + rA) * SSn;
    float* arow1 = arow0 + 8 * SSn;
    const int ln8 = lane & 7, lg = lane >> 3;
    float rs0 = 0.f, rs1 = 0.f;

    for (int c = 0; c < 32; ++c) {
        if (c < 31) {                                  // prefetch next chunk to regs
            #pragma unroll
            for (int i = 0; i < 4; ++i) kv[i] = Ks[(c + 1) * 1024 + tid + i * 256];
        }
        const uint32_t ba0 = sb + (uint32_t)((c & 1) * BUFSZ);

        #pragma unroll
        for (int nt = 0; nt < 8; ++nt) {
            const uint32_t ba = ba0 + (uint32_t)((nt * 8 + ln8) * ROWB + lg * 16);
            uint32_t bhf[4][2], blf[4][2], t4[4];
            ldsm4(t4, ba);
            bhf[0][0] = t4[0]; bhf[0][1] = t4[1]; bhf[1][0] = t4[2]; bhf[1][1] = t4[3];
            ldsm4(t4, ba + 64);
            bhf[2][0] = t4[0]; bhf[2][1] = t4[1]; bhf[3][0] = t4[2]; bhf[3][1] = t4[3];
            ldsm4(t4, ba + LOFFA);
            blf[0][0] = t4[0]; blf[0][1] = t4[1]; blf[1][0] = t4[2]; blf[1][1] = t4[3];
            ldsm4(t4, ba + LOFFA + 64);
            blf[2][0] = t4[0]; blf[2][1] = t4[1]; blf[3][0] = t4[2]; blf[3][1] = t4[3];

            // bias/mask loads issue here, consumed after the MMA block
            const int col = c * 64 + nt * 8 + kA;
            float2 bb0 = *(const float2*)(brow0 + col);
            float2 mm0 = *(const float2*)(mrow0 + col);
            float2 bb1 = *(const float2*)(brow1 + col);
            float2 mm1 = *(const float2*)(mrow1 + col);

            float cc[4] = {0.f, 0.f, 0.f, 0.f};
            #pragma unroll
            for (int ks = 0; ks < 4; ++ks) mma16816(cc, a_hi[ks], bhf[ks]);
            #pragma unroll
            for (int ks = 0; ks < 4; ++ks) mma16816(cc, a_hi[ks], blf[ks]);
            #pragma unroll
            for (int ks = 0; ks < 4; ++ks) mma16816(cc, a_lo[ks], bhf[ks]);

            float e0 = ex2((cc[0] + bb0.x + mm0.x) * L2E);
            float e1 = ex2((cc[1] + bb0.y + mm0.y) * L2E);
            float e2 = ex2((cc[2] + bb1.x + mm1.x) * L2E);
            float e3 = ex2((cc[3] + bb1.y + mm1.y) * L2E);
            rs0 += e0 + e1;
            rs1 += e2 + e3;
            *(float2*)(arow0 + col) = make_float2(e0, e1);
            *(float2*)(arow1 + col) = make_float2(e2, e3);
        }

        if (c < 31) {                                  // store prefetched chunk to other buffer
            char* bp = sK + ((c + 1) & 1) * BUFSZ;
            #pragma unroll
            for (int i = 0; i < 4; ++i) {
                int f4 = tid + i * 256, row = f4 >> 4, c4 = f4 & 15;
                uint32_t h0, l0, h1, l1;
                split2(kv[i].x, kv[i].y, h0, l0);
                split2(kv[i].z, kv[i].w, h1, l1);
                char* d = bp + row * ROWB + c4 * 8;
                *(uint2*)d = make_uint2(h0, h1);
                *(uint2*)(d + LOFFA) = make_uint2(l0, l1);
            }
        }
        __syncthreads();
    }

    rs0 += __shfl_xor_sync(0xffffffffu, rs0, 1);
    rs0 += __shfl_xor_sync(0xffffffffu, rs0, 2);
    rs1 += __shfl_xor_sync(0xffffffffu, rs1, 1);
    rs1 += __shfl_xor_sync(0xffffffffu, rs1, 2);
    if ((lane & 3) == 0) {
        g_inv[(size_t)bh * SSn + q0 + rA] = 1.f / rs0;
        g_inv[(size_t)bh * SSn + q0 + rA + 8] = 1.f / rs1;
    }
}

// =====================================================================
// Kernel B: normalize Attn in place (required output) + Out = P @ V
// 64-k chunks double-buffered; P fragments prefetched one k-step ahead.
// =====================================================================
__global__ __launch_bounds__(256) void attn_pv_kernel(
    const float* __restrict__ V, float* __restrict__ Attn, float* __restrict__ Out)
{
    __shared__ __align__(16) char sV[2 * BUFSZ];

    const int tid = threadIdx.x, wid = tid >> 5, lane = tid & 31;
    const int b = blockIdx.x, h = blockIdx.y, qt = blockIdx.z;
    const int bh = b * HHn + h, q0 = qt * 128;
    const int rA = wid * 16 + (lane >> 2);
    const int kA = (lane & 3) * 2;

    const float inv0 = g_inv[(size_t)bh * SSn + q0 + rA];
    const float inv1 = g_inv[(size_t)bh * SSn + q0 + rA + 8];

    float acc[8][4];
    #pragma unroll
    for (int n = 0; n < 8; ++n)
        #pragma unroll
        for (int j = 0; j < 4; ++j) acc[n][j] = 0.f;

    float* prow0 = Attn + ((size_t)bh * SSn + q0 + rA) * SSn;
    float* prow1 = prow0 + 8 * SSn;
    const float4* Vs = (const float4*)(V + (size_t)bh * SSn * DDn);
    const uint32_t sb = smem_u32(sV);
    const int ln8 = lane & 7, lg1 = (lane >> 3) & 1, lg2 = lane >> 4;

    float4 vv[4];
    #pragma unroll
    for (int i = 0; i < 4; ++i) vv[i] = Vs[tid + i * 256];        // chunk 0
    {
        #pragma unroll
        for (int i = 0; i < 4; ++i) {
            int f4 = tid + i * 256, row = f4 >> 4, c4 = f4 & 15;
            uint32_t h0, l0, h1, l1;
            split2(vv[i].x, vv[i].y, h0, l0);
            split2(vv[i].z, vv[i].w, h1, l1);
            char* d = sV + row * ROWB + c4 * 8;
            *(uint2*)d = make_uint2(h0, h1);
            *(uint2*)(d + LOFFA) = make_uint2(l0, l1);
        }
    }
    __syncthreads();

    // P prefetch for kcol = 0
    float2 pf0 = *(float2*)(prow0 + kA);
    float2 pf1 = *(float2*)(prow1 + kA);
    float2 pf2 = *(float2*)(prow0 + 8 + kA);
    float2 pf3 = *(float2*)(prow1 + 8 + kA);

    for (int c = 0; c < 32; ++c) {
        if (c < 31) {
            #pragma unroll
            for (int i = 0; i < 4; ++i) vv[i] = Vs[(c + 1) * 1024 + tid + i * 256];
        }
        const uint32_t ba0 = sb + (uint32_t)((c & 1) * BUFSZ);

        #pragma unroll
        for (int ks = 0; ks < 4; ++ks) {
            const int kcol = c * 64 + ks * 16;

            // prefetch next k-step's P fragments (contiguous along k)
            float2 np0, np1, np2, np3;
            if (kcol < 2032) {
                np0 = *(float2*)(prow0 + kcol + 16 + kA);
                np1 = *(float2*)(prow1 + kcol + 16 + kA);
                np2 = *(float2*)(prow0 + kcol + 24 + kA);
                np3 = *(float2*)(prow1 + kcol + 24 + kA);
            }

            // normalize current P, write back (required attn output), split to frags
            uint32_t ahi[4], alo[4];
            pf0.x *= inv0; pf0.y *= inv0;
            *(float2*)(prow0 + kcol + kA) = pf0; split2(pf0.x, pf0.y, ahi[0], alo[0]);
            pf1.x *= inv1; pf1.y *= inv1;
            *(float2*)(prow1 + kcol + kA) = pf1; split2(pf1.x, pf1.y, ahi[1], alo[1]);
            pf2.x *= inv0; pf2.y *= inv0;
            *(float2*)(prow0 + kcol + 8 + kA) = pf2; split2(pf2.x, pf2.y, ahi[2], alo[2]);
            pf3.x *= inv1; pf3.y *= inv1;
            *(float2*)(prow1 + kcol + 8 + kA) = pf3; split2(pf3.x, pf3.y, ahi[3], alo[3]);

            const uint32_t ka = ba0 + (uint32_t)((ks * 16 + lg1 * 8 + ln8) * ROWB + lg2 * 16);
            #pragma unroll
            for (int np = 0; np < 4; ++np) {
                uint32_t t4[4], u4[4];
                ldsm4t(t4, ka + np * 32);          // V hi : n-tiles 2np, 2np+1
                ldsm4t(u4, ka + np * 32 + LOFFA);  // V lo
                mma16816(acc[2 * np],     ahi, &t4[0]);
                mma16816(acc[2 * np + 1], ahi, &t4[2]);
                mma16816(acc[2 * np],     ahi, &u4[0]);
                mma16816(acc[2 * np + 1], ahi, &u4[2]);
                mma16816(acc[2 * np],     alo, &t4[0]);
                mma16816(acc[2 * np + 1], alo, &t4[2]);
            }
            pf0 = np0; pf1 = np1; pf2 = np2; pf3 = np3;
        }

        if (c < 31) {
            char* bp = sV + ((c + 1) & 1) * BUFSZ;
            #pragma unroll
            for (int i = 0; i < 4; ++i) {
                int f4 = tid + i * 256, row = f4 >> 4, c4 = f4 & 15;
                uint32_t h0, l0, h1, l1;
                split2(vv[i].x, vv[i].y, h0, l0);
                split2(vv[i].z, vv[i].w, h1, l1);
                char* d = bp + row * ROWB + c4 * 8;
                *(uint2*)d = make_uint2(h0, h1);
                *(uint2*)(d + LOFFA) = make_uint2(l0, l1);
            }
        }
        __syncthreads();
    }

    float* orow0 = Out + ((size_t)bh * SSn + q0 + rA) * DDn;
    float* orow1 = orow0 + 8 * DDn;
    #pragma unroll
    for (int nt = 0; nt < 8; ++nt) {
        *(float2*)(orow0 + nt * 8 + kA) = make_float2(acc[nt][0], acc[nt][1]);
        *(float2*)(orow1 + nt * 8 + kA) = make_float2(acc[nt][2], acc[nt][3]);
    }
}

extern "C" void kernel_launch(void* const* d_in, const int* in_sizes, int n_in,
                              void* d_out, int out_size)
{
    const float* Q    = (const float*)d_in[0];
    const float* K    = (const float*)d_in[1];
    const float* V    = (const float*)d_in[2];
    const float* Bias = (const float*)d_in[3];
    const float* Mask = (const float*)d_in[4];
    float* Out  = (float*)d_out;
    float* Attn = Out + (size_t)BBn * HHn * SSn * DDn;

    dim3 grid(BBn, HHn, SSn / 128);   // b fastest -> bias L2 reuse
    attn_scores_kernel<<<grid, 256>>>(Q, K, Bias, Mask, Attn);
    attn_pv_kernel<<<grid, 256>>>(V, Attn, Out);
}

// round 7
// speedup vs baseline: 2.0770x; 2.0770x over previous
#include <cuda_runtime.h>
#include <cuda_bf16.h>
#include <cstdint>

#define SSn 2048
#define DDn 64
#define HHn 16
#define BBn 4
#define L2E 1.4426950408889634f

#define ROWB 144
#define KLO 18432          // K lo-plane offset
#define VHI 36864          // V hi-plane
#define VLO 18432          // V lo is VHI + VLO
#define SINV 73728
#define SMEMB 74240

__device__ __forceinline__ uint32_t smem_u32(const void* p) {
    uint32_t a;
    asm("{ .reg .u64 t; cvta.to.shared.u64 t, %1; cvt.u32.u64 %0, t; }" : "=r"(a) : "l"(p));
    return a;
}
__device__ __forceinline__ void mma16816(float* c, const uint32_t* a, const uint32_t* b) {
    asm volatile("mma.sync.aligned.m16n8k16.row.col.f32.bf16.bf16.f32 "
        "{%0,%1,%2,%3}, {%4,%5,%6,%7}, {%8,%9}, {%0,%1,%2,%3};"
        : "+f"(c[0]), "+f"(c[1]), "+f"(c[2]), "+f"(c[3])
        : "r"(a[0]), "r"(a[1]), "r"(a[2]), "r"(a[3]), "r"(b[0]), "r"(b[1]));
}
__device__ __forceinline__ void ldsm4(uint32_t* r, uint32_t a) {
    asm volatile("ldmatrix.sync.aligned.m8n8.x4.shared.b16 {%0,%1,%2,%3}, [%4];"
        : "=r"(r[0]), "=r"(r[1]), "=r"(r[2]), "=r"(r[3]) : "r"(a));
}
__device__ __forceinline__ void ldsm4t(uint32_t* r, uint32_t a) {
    asm volatile("ldmatrix.sync.aligned.m8n8.x4.trans.shared.b16 {%0,%1,%2,%3}, [%4];"
        : "=r"(r[0]), "=r"(r[1]), "=r"(r[2]), "=r"(r[3]) : "r"(a));
}
__device__ __forceinline__ void split2(float x, float y, uint32_t& hp, uint32_t& lp) {
    __nv_bfloat162 h2 = __float22bfloat162_rn(make_float2(x, y));
    float2 hf = __bfloat1622float2(h2);
    __nv_bfloat162 l2 = __float22bfloat162_rn(make_float2(x - hf.x, y - hf.y));
    hp = *reinterpret_cast<uint32_t*>(&h2);
    lp = *reinterpret_cast<uint32_t*>(&l2);
}
__device__ __forceinline__ float ex2(float x) {
    float y; asm("ex2.approx.f32 %0, %1;" : "=f"(y) : "f"(x)); return y;
}

__global__ __launch_bounds__(256, 2) void attn_fused(
    const float* __restrict__ Q, const float* __restrict__ K,
    const float* __restrict__ V, const float* __restrict__ Bias,
    const float* __restrict__ Mask,
    float* __restrict__ Out, float* __restrict__ Attn)
{
    extern __shared__ char sm[];
    float* sInv = (float*)(sm + SINV);

    const int tid = threadIdx.x, wid = tid >> 5, lane = tid & 31;
    const int b = blockIdx.x, h = blockIdx.y, qt = blockIdx.z;
    const int bh = b * HHn + h, q0 = qt * 128;
    const int rA = wid * 16 + (lane >> 2);
    const int kA = (lane & 3) * 2;

    // ---- Q A-fragments (scaled 1/8, split hi/lo, register-resident)
    uint32_t qhi[4][4], qlo[4][4];
    {
        const float* q_r0 = Q + ((size_t)bh * SSn + q0 + rA) * DDn;
        const float* q_r1 = q_r0 + 8 * DDn;
        #pragma unroll
        for (int ks = 0; ks < 4; ++ks) {
            float2 v;
            v = *(const float2*)(q_r0 + ks * 16 + kA);
            split2(v.x * 0.125f, v.y * 0.125f, qhi[ks][0], qlo[ks][0]);
            v = *(const float2*)(q_r1 + ks * 16 + kA);
            split2(v.x * 0.125f, v.y * 0.125f, qhi[ks][1], qlo[ks][1]);
            v = *(const float2*)(q_r0 + ks * 16 + 8 + kA);
            split2(v.x * 0.125f, v.y * 0.125f, qhi[ks][2], qlo[ks][2]);
            v = *(const float2*)(q_r1 + ks * 16 + 8 + kA);
            split2(v.x * 0.125f, v.y * 0.125f, qhi[ks][3], qlo[ks][3]);
        }
    }

    const uint32_t sb = smem_u32(sm);
    const float4* Ks = (const float4*)(K + (size_t)bh * SSn * DDn);
    const float4* Vs = (const float4*)(V + (size_t)bh * SSn * DDn);
    const float* brow0 = Bias + ((size_t)h * SSn + q0 + rA) * SSn;
    const float* brow1 = brow0 + 8 * SSn;
    const float* mrow0 = Mask + ((size_t)b * SSn + q0 + rA) * SSn;
    const float* mrow1 = mrow0 + 8 * SSn;
    float* arow0 = Attn + ((size_t)bh * SSn + q0 + rA) * SSn;
    float* arow1 = arow0 + 8 * SSn;

    const int ln8 = lane & 7, lg = lane >> 3;
    const int lg1 = (lane >> 3) & 1, lg2 = lane >> 4;

    float rs0 = 0.f, rs1 = 0.f;
    float acc[8][4];
    #pragma unroll
    for (int n = 0; n < 8; ++n)
        #pragma unroll
        for (int j = 0; j < 4; ++j) acc[n][j] = 0.f;

    for (int c = 0; c < 16; ++c) {
        __syncthreads();
        #pragma unroll
        for (int i = 0; i < 8; ++i) {         // K chunk: 128 keys x 64 d
            int f4 = tid + i * 256, row = f4 >> 4, c4 = f4 & 15;
            float4 v = Ks[c * 2048 + f4];
            uint32_t h0, l0, h1, l1;
            split2(v.x, v.y, h0, l0);
            split2(v.z, v.w, h1, l1);
            char* d = sm + row * ROWB + c4 * 8;
            *(uint2*)d = make_uint2(h0, h1);
            *(uint2*)(d + KLO) = make_uint2(l0, l1);
        }
        #pragma unroll
        for (int i = 0; i < 8; ++i) {         // V chunk
            int f4 = tid + i * 256, row = f4 >> 4, c4 = f4 & 15;
            float4 v = Vs[c * 2048 + f4];
            uint32_t h0, l0, h1, l1;
            split2(v.x, v.y, h0, l0);
            split2(v.z, v.w, h1, l1);
            char* d = sm + VHI + row * ROWB + c4 * 8;
            *(uint2*)d = make_uint2(h0, h1);
            *(uint2*)(d + VLO) = make_uint2(l0, l1);
        }
        __syncthreads();

        #pragma unroll
        for (int g = 0; g < 8; ++g) {         // 16-key groups
            float eA[4], eB[4];
            #pragma unroll
            for (int hf = 0; hf < 2; ++hf) {
                const int nt = g * 2 + hf;
                const uint32_t ba = sb + (uint32_t)((nt * 8 + ln8) * ROWB + lg * 16);
                uint32_t bhf[4][2], blf[4][2], t4[4];
                ldsm4(t4, ba);
                bhf[0][0] = t4[0]; bhf[0][1] = t4[1]; bhf[1][0] = t4[2]; bhf[1][1] = t4[3];
                ldsm4(t4, ba + 64);
                bhf[2][0] = t4[0]; bhf[2][1] = t4[1]; bhf[3][0] = t4[2]; bhf[3][1] = t4[3];
                ldsm4(t4, ba + KLO);
                blf[0][0] = t4[0]; blf[0][1] = t4[1]; blf[1][0] = t4[2]; blf[1][1] = t4[3];
                ldsm4(t4, ba + KLO + 64);
                blf[2][0] = t4[0]; blf[2][1] = t4[1]; blf[3][0] = t4[2]; blf[3][1] = t4[3];

                const int col = c * 128 + nt * 8 + kA;
                float2 bb0 = *(const float2*)(brow0 + col);
                float2 mm0 = *(const float2*)(mrow0 + col);
                float2 bb1 = *(const float2*)(brow1 + col);
                float2 mm1 = *(const float2*)(mrow1 + col);

                float cc[4] = {0.f, 0.f, 0.f, 0.f};
                #pragma unroll
                for (int ks = 0; ks < 4; ++ks) mma16816(cc, qhi[ks], bhf[ks]);
                #pragma unroll
                for (int ks = 0; ks < 4; ++ks) mma16816(cc, qhi[ks], blf[ks]);
                #pragma unroll
                for (int ks = 0; ks < 4; ++ks) mma16816(cc, qlo[ks], bhf[ks]);

                float* e = hf ? eB : eA;
                e[0] = ex2((cc[0] + bb0.x + mm0.x) * L2E);
                e[1] = ex2((cc[1] + bb0.y + mm0.y) * L2E);
                e[2] = ex2((cc[2] + bb1.x + mm1.x) * L2E);
                e[3] = ex2((cc[3] + bb1.y + mm1.y) * L2E);
                rs0 += e[0] + e[1];
                rs1 += e[2] + e[3];
                *(float2*)(arow0 + col) = make_float2(e[0], e[1]);
                *(float2*)(arow1 + col) = make_float2(e[2], e[3]);
            }

            // ---- P fragment (exp values ARE the next A-fragment) + PV MMAs
            uint32_t ahi[4], alo[4];
            split2(eA[0], eA[1], ahi[0], alo[0]);
            split2(eA[2], eA[3], ahi[1], alo[1]);
            split2(eB[0], eB[1], ahi[2], alo[2]);
            split2(eB[2], eB[3], ahi[3], alo[3]);

            const uint32_t ka = sb + VHI +
                (uint32_t)((g * 16 + lg1 * 8 + ln8) * ROWB + lg2 * 16);
            #pragma unroll
            for (int np = 0; np < 4; ++np) {
                uint32_t t4[4], u4[4];
                ldsm4t(t4, ka + np * 32);          // V hi : d-tiles 2np, 2np+1
                ldsm4t(u4, ka + np * 32 + VLO);    // V lo
                mma16816(acc[2 * np],     ahi, &t4[0]);
                mma16816(acc[2 * np + 1], ahi, &t4[2]);
                mma16816(acc[2 * np],     ahi, &u4[0]);
                mma16816(acc[2 * np + 1], ahi, &u4[2]);
                mma16816(acc[2 * np],     alo, &t4[0]);
                mma16816(acc[2 * np + 1], alo, &t4[2]);
            }
        }
    }

    // ---- row-sum inverses
    rs0 += __shfl_xor_sync(0xffffffffu, rs0, 1);
    rs0 += __shfl_xor_sync(0xffffffffu, rs0, 2);
    rs1 += __shfl_xor_sync(0xffffffffu, rs1, 1);
    rs1 += __shfl_xor_sync(0xffffffffu, rs1, 2);
    if ((lane & 3) == 0) {
        sInv[rA] = 1.f / rs0;
        sInv[rA + 8] = 1.f / rs1;
    }
    __syncthreads();
    const float inv0 = sInv[rA], inv1 = sInv[rA + 8];

    // ---- Out = acc * inv
    float* orow0 = Out + ((size_t)bh * SSn + q0 + rA) * DDn;
    float* orow1 = orow0 + 8 * DDn;
    #pragma unroll
    for (int nt = 0; nt < 8; ++nt) {
        *(float2*)(orow0 + nt * 8 + kA) = make_float2(acc[nt][0] * inv0, acc[nt][1] * inv0);
        *(float2*)(orow1 + nt * 8 + kA) = make_float2(acc[nt][2] * inv1, acc[nt][3] * inv1);
    }

    // ---- normalize the attn tile in place (coalesced float4, partially L2-hot)
    float* tile = Attn + ((size_t)bh * SSn + q0) * SSn;
    #pragma unroll 4
    for (int i = 0; i < 256; ++i) {
        int idx = tid + i * 256;
        int row = idx >> 9, c4 = idx & 511;
        float4* p = ((float4*)(tile + (size_t)row * SSn)) + c4;
        float4 v = *p;
        const float inv = sInv[row];
        v.x *= inv; v.y *= inv; v.z *= inv; v.w *= inv;
        *p = v;
    }
}

extern "C" void kernel_launch(void* const* d_in, const int* in_sizes, int n_in,
                              void* d_out, int out_size)
{
    const float* Q    = (const float*)d_in[0];
    const float* K    = (const float*)d_in[1];
    const float* V    = (const float*)d_in[2];
    const float* Bias = (const float*)d_in[3];
    const float* Mask = (const float*)d_in[4];
    float* Out  = (float*)d_out;
    float* Attn = Out + (size_t)BBn * HHn * SSn * DDn;

    cudaFuncSetAttribute(attn_fused, cudaFuncAttributeMaxDynamicSharedMemorySize, SMEMB);
    dim3 grid(BBn, HHn, SSn / 128);   // b fastest -> bias L2 reuse
    attn_fused<<<grid, 256, SMEMB>>>(Q, K, V, Bias, Mask, Out, Attn);
}